// round 14
// baseline (speedup 1.0000x reference)
#include <cuda_runtime.h>
#include <cuda_fp16.h>
#include <cstdint>

// Problem constants (fixed shapes per reference)
#define C_    64
#define D_    8
#define K15_  15
#define K16_  16
#define OUTW  512
#define MAXB  32768
#define NJT   8               // j-tiles of 64
#define ROWB  128             // 64 j fp16 per row
#define TROWS 1024            // c*16+e rows per tile
#define TILEB (TROWS * ROWB)  // 131072 B: one jt tile, smem-resident
#define GCH   128             // b per gather chunk
#define GY    18              // CTAs per jt
#define NCTA  (NJT * GY)      // 144 persistent CTAs (all co-resident, <=148 SMs)

// Scratch (no cudaMalloc allowed): zero-initialized device globals.
__device__ uint8_t        g_table[1 << K15_];   // sign pattern -> argmax_j
__device__ unsigned short g_poff[MAXB * C_];    // (b,c) -> e*128 (row byte off)
__device__ unsigned       g_bar_cnt[2];         // grid barrier arrive counters
__device__ unsigned       g_bar_rel[2];         // grid barrier release words (monotonic)

__device__ __forceinline__ void cp16(uint32_t daddr, const void* src) {
    asm volatile("cp.async.cg.shared.global [%0], [%1], 16;" :: "r"(daddr), "l"(src) : "memory");
}

// Replay-safe grid barrier: all NCTA CTAs are wave-1 co-resident (1 CTA/SM,
// 144 <= 148). Release word is monotonic; spinners compare against the value
// read BEFORE arriving, so state never needs resetting across graph replays
// (arrive counter is reset by the last arriver).
__device__ __forceinline__ void grid_barrier(int slot) {
    __syncthreads();
    __threadfence();
    if (threadIdx.x == 0) {
        volatile unsigned* rel = &g_bar_rel[slot];
        const unsigned cur = *rel;
        const unsigned old = atomicAdd(&g_bar_cnt[slot], 1);
        if (old == NCTA - 1) {
            g_bar_cnt[slot] = 0;
            __threadfence();
            *rel = cur + 1;
        } else {
            while (*rel == cur) {}
        }
    }
    __syncthreads();
    __threadfence();
}

// ---------------------------------------------------------------------------
// smem layout (dynamic, 165 KB):
//   [0, 32768)        stage B: S_s (8192 f32, [c][d][16])  | stage C: id bufs (2 x 16 KB)
//   [32768, 36608)    T_s (960 f32)
//   [36608, 37568)    Hs  (240 f32)
//   [37888, +131072)  jt tile (fp16, 1024 rows x 128 B)
// ---------------------------------------------------------------------------
#define IDB0  0u
#define IDB1  16384u
#define TS_OFF 32768
#define HS_OFF 36608
#define TOFF  37888u
#define GSMEM (TOFF + TILEB)

__global__ void __launch_bounds__(1024, 1) fused_kernel(const float* __restrict__ x,
                                                        const float* __restrict__ S,
                                                        const float* __restrict__ T,
                                                        const float* __restrict__ H,
                                                        const float* __restrict__ LUT,
                                                        float* __restrict__ out, int B) {
    extern __shared__ char smem[];
    float* S_s = (float*)smem;
    float* T_s = (float*)(smem + TS_OFF);
    float* Hs  = (float*)(smem + HS_OFF);

    const int tid = threadIdx.x, w = tid >> 5, lane = tid & 31;
    const int bid = blockIdx.x;
    const int jt = bid & 7;
    const uint32_t sb = (uint32_t)__cvta_generic_to_shared(smem);

    // ======================= Stage A =======================
    // Stage H, T, S into smem (S padded [c][d][16])
    if (tid < K15_ * K16_) Hs[tid] = H[tid];
    for (int i = tid; i < C_ * K15_; i += 1024) T_s[i] = T[i];
    for (int i = tid; i < C_ * D_ * K15_; i += 1024) {
        int cd = i / K15_, k = i - cd * K15_;
        S_s[cd * 16 + k] = S[i];
    }
    __syncthreads();

    // argmax table: CTAs 0..31 cover all 32768 patterns (overlaps tile loads below)
    {
        const int m = bid * 1024 + tid;
        if (m < (1 << K15_)) {
            float h[K16_];
#pragma unroll
            for (int j = 0; j < K16_; j++) h[j] = 0.f;
#pragma unroll
            for (int k = 0; k < K15_; k++) {
                float sgn = ((m >> k) & 1) ? 1.f : -1.f;
#pragma unroll
                for (int j = 0; j < K16_; j++) h[j] += sgn * Hs[k * K16_ + j];
            }
            float best = h[0];
            int   bi = 0;
#pragma unroll
            for (int j = 1; j < K16_; j++)
                if (h[j] > best) { best = h[j]; bi = j; }
            g_table[m] = (uint8_t)bi;
        }
    }

    // convert own jt tile fp32 -> fp16 directly from LUT (no global staging)
    {
        const int seg = tid & 15;   // 16 x float4 per 64-j row slice
#pragma unroll
        for (int it = 0; it < 16; it++) {
            const int row = (tid >> 4) + it * 64;
            const float4 a = __ldg((const float4*)(LUT + (size_t)row * OUTW + jt * 64 + seg * 4));
            __half2 h0 = __floats2half2_rn(a.x, a.y);
            __half2 h1 = __floats2half2_rn(a.z, a.w);
            uint2 v;
            v.x = *(uint32_t*)&h0; v.y = *(uint32_t*)&h1;
            *(uint2*)(smem + TOFF + (size_t)row * ROWB + seg * 8) = v;
        }
    }

    grid_barrier(0);   // table + tiles + S/T visible everywhere

    // ======================= Stage B: idx =======================
    // unit = (32-b group, 8-c group); lane = b within group. Same math as before.
    {
        const int nbg = (B + 31) / 32;
        const int units = nbg * 8;
        for (int u = bid * 32 + w; u < units; u += NCTA * 32) {
            const int bg = u >> 3, cg = u & 7;
            const int b = bg * 32 + lane;
            const float* xrow = x + (size_t)((b < B) ? b : 0) * 512;

            int e8[8];
#pragma unroll
            for (int cc = 0; cc < 8; cc++) {
                const int c = cg * 8 + cc;
                const float4 xa = __ldg((const float4*)(xrow + c * 8));
                const float4 xb = __ldg((const float4*)(xrow + c * 8 + 4));
                float xr[D_] = {xa.x, xa.y, xa.z, xa.w, xb.x, xb.y, xb.z, xb.w};
                float acc[16];
#pragma unroll
                for (int k = 0; k < 16; k++) acc[k] = 0.f;
#pragma unroll
                for (int d = 0; d < D_; d++) {
                    const float xd = xr[d];
                    const float4* s4 = (const float4*)(S_s + (c * D_ + d) * 16);
                    const float4 s0 = s4[0], s1 = s4[1], s2 = s4[2], s3 = s4[3];
                    acc[0]  += xd * s0.x; acc[1]  += xd * s0.y; acc[2]  += xd * s0.z; acc[3]  += xd * s0.w;
                    acc[4]  += xd * s1.x; acc[5]  += xd * s1.y; acc[6]  += xd * s1.z; acc[7]  += xd * s1.w;
                    acc[8]  += xd * s2.x; acc[9]  += xd * s2.y; acc[10] += xd * s2.z; acc[11] += xd * s2.w;
                    acc[12] += xd * s3.x; acc[13] += xd * s3.y; acc[14] += xd * s3.z;
                }
                unsigned m = 0;
#pragma unroll
                for (int k = 0; k < K15_; k++)
                    if (acc[k] > T_s[c * K15_ + k]) m |= (1u << k);
                e8[cc] = g_table[m];
            }

            if (b < B) {
                uint4 pk;
                pk.x = (uint32_t)(e8[0] << 7) | ((uint32_t)(e8[1] << 7) << 16);
                pk.y = (uint32_t)(e8[2] << 7) | ((uint32_t)(e8[3] << 7) << 16);
                pk.z = (uint32_t)(e8[4] << 7) | ((uint32_t)(e8[5] << 7) << 16);
                pk.w = (uint32_t)(e8[6] << 7) | ((uint32_t)(e8[7] << 7) << 16);
                *(uint4*)(g_poff + (size_t)b * C_ + cg * 8) = pk;
            }
        }
    }

    grid_barrier(1);   // all ids visible; S_s region now dead -> id buffers

    // ======================= Stage C: gather =======================
    const int half = lane >> 4, l16 = lane & 15;
    const int nch = (B + GCH - 1) / GCH;
    const char* tile = smem + TOFF + l16 * 8;   // lane's 8B j-slice within each row

    // ids for first chunk
    {
        const unsigned char* ip = (const unsigned char*)g_poff + (size_t)(bid >> 3) * GCH * 128;
        cp16(sb + IDB0 + tid * 16, ip + tid * 16);
        asm volatile("cp.async.commit_group;" ::: "memory");
        asm volatile("cp.async.wait_group 0;" ::: "memory");
    }
    __syncthreads();

    int ch = bid >> 3;          // 0..17
    uint32_t bufo = IDB0;
    while (ch < nch) {
        const int nx = ch + GY;
        if (nx < nch) {
            const uint32_t nbo = bufo ^ (IDB0 ^ IDB1);
            const unsigned char* ip = (const unsigned char*)g_poff + (size_t)nx * GCH * 128;
            cp16(sb + nbo + tid * 16, ip + tid * 16);
            asm volatile("cp.async.commit_group;" ::: "memory");
        }

        const int bbase = ch * GCH;
#pragma unroll
        for (int i = 0; i < 2; i++) {
            const int bl = w * 4 + 2 * i + half;
            const uint4* idp = (const uint4*)(smem + bufo + bl * 128);
            float4 a = make_float4(0.f, 0.f, 0.f, 0.f);
#pragma unroll
            for (int c8 = 0; c8 < 8; c8++) {
                const uint4 id8 = idp[c8];                       // LDS.128 broadcast / half
                const uint32_t o0 = id8.x & 0xFFFFu, o1 = id8.x >> 16;
                const uint32_t o2 = id8.y & 0xFFFFu, o3 = id8.y >> 16;
                const uint32_t o4 = id8.z & 0xFFFFu, o5 = id8.z >> 16;
                const uint32_t o6 = id8.w & 0xFFFFu, o7 = id8.w >> 16;
                const char* cb = tile + (size_t)(c8 * 8) * 2048;
                const uint2 v0 = *(const uint2*)(cb + o0 + 0 * 2048);
                const uint2 v1 = *(const uint2*)(cb + o1 + 1 * 2048);
                const uint2 v2 = *(const uint2*)(cb + o2 + 2 * 2048);
                const uint2 v3 = *(const uint2*)(cb + o3 + 3 * 2048);
                const uint2 v4 = *(const uint2*)(cb + o4 + 4 * 2048);
                const uint2 v5 = *(const uint2*)(cb + o5 + 5 * 2048);
                const uint2 v6 = *(const uint2*)(cb + o6 + 6 * 2048);
                const uint2 v7 = *(const uint2*)(cb + o7 + 7 * 2048);
                {
                    __half2 s0 = __hadd2(__hadd2(*(const __half2*)&v0.x, *(const __half2*)&v1.x),
                                         __hadd2(*(const __half2*)&v2.x, *(const __half2*)&v3.x));
                    __half2 s1 = __hadd2(__hadd2(*(const __half2*)&v0.y, *(const __half2*)&v1.y),
                                         __hadd2(*(const __half2*)&v2.y, *(const __half2*)&v3.y));
                    const float2 f0 = __half22float2(s0);
                    const float2 f1 = __half22float2(s1);
                    a.x += f0.x; a.y += f0.y; a.z += f1.x; a.w += f1.y;
                }
                {
                    __half2 s0 = __hadd2(__hadd2(*(const __half2*)&v4.x, *(const __half2*)&v5.x),
                                         __hadd2(*(const __half2*)&v6.x, *(const __half2*)&v7.x));
                    __half2 s1 = __hadd2(__hadd2(*(const __half2*)&v4.y, *(const __half2*)&v5.y),
                                         __hadd2(*(const __half2*)&v6.y, *(const __half2*)&v7.y));
                    const float2 f0 = __half22float2(s0);
                    const float2 f1 = __half22float2(s1);
                    a.x += f0.x; a.y += f0.y; a.z += f1.x; a.w += f1.y;
                }
            }
            const int b = bbase + bl;
            if (b < B)
                *(float4*)(out + (size_t)b * OUTW + jt * 64 + l16 * 4) = a;
        }

        if (nx >= nch) break;
        asm volatile("cp.async.wait_group 0;" ::: "memory");
        __syncthreads();
        bufo ^= (IDB0 ^ IDB1);
        ch = nx;
    }
}

// ---------------------------------------------------------------------------
extern "C" void kernel_launch(void* const* d_in, const int* in_sizes, int n_in,
                              void* d_out, int out_size) {
    const float* x   = (const float*)d_in[0];
    const float* S   = (const float*)d_in[1];
    const float* H   = (const float*)d_in[2];
    const float* T   = (const float*)d_in[3];
    const float* LUT = (const float*)d_in[4];
    float*       out = (float*)d_out;

    const int B = in_sizes[0] / (C_ * D_);

    cudaFuncSetAttribute(fused_kernel, cudaFuncAttributeMaxDynamicSharedMemorySize, GSMEM);
    fused_kernel<<<NCTA, 1024, GSMEM>>>(x, S, T, H, LUT, out, B);
}

// round 15
// speedup vs baseline: 1.0056x; 1.0056x over previous
#include <cuda_runtime.h>
#include <cuda_fp16.h>
#include <cstdint>

// Problem constants (fixed shapes per reference)
#define C_    64
#define D_    8
#define K15_  15
#define K16_  16
#define OUTW  512
#define MAXB  32768
#define NJT   8               // j-tiles of 64
#define ROWB  128             // 64 j fp16 per row
#define TROWS 1024            // c*16+e rows per tile
#define TILEB (TROWS * ROWB)  // 131072 B: one jt tile, smem-resident
#define GCH   128             // b per gather chunk
#define GY    18              // CTAs per jt
#define NCTA  (NJT * GY)      // 144 persistent CTAs (all co-resident, <=148 SMs)

// Scratch (no cudaMalloc allowed): zero-initialized device globals.
__device__ uint8_t        g_table[1 << K15_];   // sign pattern -> argmax_j
__device__ unsigned short g_poff[MAXB * C_];    // (b,c) -> e*128 (row byte off)
__device__ unsigned       g_bar_cnt[2];         // grid barrier arrive counters
__device__ unsigned       g_bar_rel[2];         // grid barrier release words (monotonic)

__device__ __forceinline__ void cp16(uint32_t daddr, const void* src) {
    asm volatile("cp.async.cg.shared.global [%0], [%1], 16;" :: "r"(daddr), "l"(src) : "memory");
}

// Replay-safe grid barrier (all NCTA CTAs wave-1 co-resident; monotonic release).
__device__ __forceinline__ void grid_barrier(int slot) {
    __syncthreads();
    __threadfence();
    if (threadIdx.x == 0) {
        volatile unsigned* rel = &g_bar_rel[slot];
        const unsigned cur = *rel;
        const unsigned old = atomicAdd(&g_bar_cnt[slot], 1);
        if (old == NCTA - 1) {
            g_bar_cnt[slot] = 0;
            __threadfence();
            *rel = cur + 1;
        } else {
            while (*rel == cur) {}
        }
    }
    __syncthreads();
    __threadfence();
}

// ---------------------------------------------------------------------------
// smem layout (dynamic, ~165 KB):
//   [0, 32768)        stage B: S_s ([c][d][16] f32) | stage C: id bufs (2 x 16 KB)
//   [32768, 36608)    T_s (960 f32)
//   [36608, 37568)    Hs  (240 f32)
//   [37888, +131072)  jt tile (fp16, 1024 rows x 128 B)
// ---------------------------------------------------------------------------
#define IDB0  0u
#define IDB1  16384u
#define TS_OFF 32768
#define HS_OFF 36608
#define TOFF  37888u
#define GSMEM (TOFF + TILEB)

__global__ void __launch_bounds__(1024, 1) fused_kernel(const float* __restrict__ x,
                                                        const float* __restrict__ S,
                                                        const float* __restrict__ T,
                                                        const float* __restrict__ H,
                                                        const float* __restrict__ LUT,
                                                        float* __restrict__ out, int B) {
    extern __shared__ char smem[];
    float* S_s = (float*)smem;
    float* T_s = (float*)(smem + TS_OFF);
    float* Hs  = (float*)(smem + HS_OFF);

    const int tid = threadIdx.x, w = tid >> 5, lane = tid & 31;
    const int bid = blockIdx.x;
    const int jt = bid & 7;
    const uint32_t sb = (uint32_t)__cvta_generic_to_shared(smem);

    // ======================= Stage A =======================
    if (tid < K15_ * K16_) Hs[tid] = H[tid];
    for (int i = tid; i < C_ * K15_; i += 1024) T_s[i] = T[i];
    for (int i = tid; i < C_ * D_ * K15_; i += 1024) {
        int cd = i / K15_, k = i - cd * K15_;
        S_s[cd * 16 + k] = S[i];
    }
    __syncthreads();

    // argmax table: CTAs 0..31 cover all 32768 patterns (overlaps tile loads)
    {
        const int m = bid * 1024 + tid;
        if (m < (1 << K15_)) {
            float h[K16_];
#pragma unroll
            for (int j = 0; j < K16_; j++) h[j] = 0.f;
#pragma unroll
            for (int k = 0; k < K15_; k++) {
                float sgn = ((m >> k) & 1) ? 1.f : -1.f;
#pragma unroll
                for (int j = 0; j < K16_; j++) h[j] += sgn * Hs[k * K16_ + j];
            }
            float best = h[0];
            int   bi = 0;
#pragma unroll
            for (int j = 1; j < K16_; j++)
                if (h[j] > best) { best = h[j]; bi = j; }
            g_table[m] = (uint8_t)bi;
        }
    }

    // convert own jt tile fp32 -> fp16 directly from LUT
    {
        const int seg = tid & 15;
#pragma unroll
        for (int it = 0; it < 16; it++) {
            const int row = (tid >> 4) + it * 64;
            const float4 a = __ldg((const float4*)(LUT + (size_t)row * OUTW + jt * 64 + seg * 4));
            __half2 h0 = __floats2half2_rn(a.x, a.y);
            __half2 h1 = __floats2half2_rn(a.z, a.w);
            uint2 v;
            v.x = *(uint32_t*)&h0; v.y = *(uint32_t*)&h1;
            *(uint2*)(smem + TOFF + (size_t)row * ROWB + seg * 8) = v;
        }
    }

    grid_barrier(0);

    // ======================= Stage B: idx (split-k, <=64 regs, no spills) ===
    {
        const int nbg = (B + 31) / 32;
        const int units = nbg * 8;
        for (int u = bid * 32 + w; u < units; u += NCTA * 32) {
            const int bg = u >> 3, cg = u & 7;
            const int b = bg * 32 + lane;
            const float* xrow = x + (size_t)((b < B) ? b : 0) * 512;

            int e8[8];
#pragma unroll
            for (int cc = 0; cc < 8; cc++) {
                const int c = cg * 8 + cc;
                const float4 xa = __ldg((const float4*)(xrow + c * 8));
                const float4 xb = __ldg((const float4*)(xrow + c * 8 + 4));
                unsigned m = 0;
                // ---- k half 0: k = 0..7 ----
                {
                    float acc[8];
#pragma unroll
                    for (int k = 0; k < 8; k++) acc[k] = 0.f;
#pragma unroll
                    for (int d = 0; d < D_; d++) {
                        const float xd = (d < 4) ? ((const float*)&xa)[d] : ((const float*)&xb)[d - 4];
                        const float4* s4 = (const float4*)(S_s + (c * D_ + d) * 16);
                        const float4 s0 = s4[0], s1 = s4[1];
                        acc[0] += xd * s0.x; acc[1] += xd * s0.y; acc[2] += xd * s0.z; acc[3] += xd * s0.w;
                        acc[4] += xd * s1.x; acc[5] += xd * s1.y; acc[6] += xd * s1.z; acc[7] += xd * s1.w;
                    }
#pragma unroll
                    for (int k = 0; k < 8; k++)
                        if (acc[k] > T_s[c * K15_ + k]) m |= (1u << k);
                }
                // ---- k half 1: k = 8..14 ----
                {
                    float acc[8];
#pragma unroll
                    for (int k = 0; k < 8; k++) acc[k] = 0.f;
#pragma unroll
                    for (int d = 0; d < D_; d++) {
                        const float xd = (d < 4) ? ((const float*)&xa)[d] : ((const float*)&xb)[d - 4];
                        const float4* s4 = (const float4*)(S_s + (c * D_ + d) * 16);
                        const float4 s2 = s4[2], s3 = s4[3];
                        acc[0] += xd * s2.x; acc[1] += xd * s2.y; acc[2] += xd * s2.z; acc[3] += xd * s2.w;
                        acc[4] += xd * s3.x; acc[5] += xd * s3.y; acc[6] += xd * s3.z;
                    }
#pragma unroll
                    for (int k = 0; k < 7; k++)
                        if (acc[k] > T_s[c * K15_ + 8 + k]) m |= (1u << (8 + k));
                }
                e8[cc] = g_table[m];
            }

            if (b < B) {
                uint4 pk;
                pk.x = (uint32_t)(e8[0] << 7) | ((uint32_t)(e8[1] << 7) << 16);
                pk.y = (uint32_t)(e8[2] << 7) | ((uint32_t)(e8[3] << 7) << 16);
                pk.z = (uint32_t)(e8[4] << 7) | ((uint32_t)(e8[5] << 7) << 16);
                pk.w = (uint32_t)(e8[6] << 7) | ((uint32_t)(e8[7] << 7) << 16);
                *(uint4*)(g_poff + (size_t)b * C_ + cg * 8) = pk;
            }
        }
    }

    grid_barrier(1);   // ids visible; S_s region now dead -> id buffers

    // ======================= Stage C: gather =======================
    const int half = lane >> 4, l16 = lane & 15;
    const int nch = (B + GCH - 1) / GCH;
    const char* tile = smem + TOFF + l16 * 8;

    {
        const unsigned char* ip = (const unsigned char*)g_poff + (size_t)(bid >> 3) * GCH * 128;
        cp16(sb + IDB0 + tid * 16, ip + tid * 16);
        asm volatile("cp.async.commit_group;" ::: "memory");
        asm volatile("cp.async.wait_group 0;" ::: "memory");
    }
    __syncthreads();

    int ch = bid >> 3;
    uint32_t bufo = IDB0;
    while (ch < nch) {
        const int nx = ch + GY;
        if (nx < nch) {
            const uint32_t nbo = bufo ^ (IDB0 ^ IDB1);
            const unsigned char* ip = (const unsigned char*)g_poff + (size_t)nx * GCH * 128;
            cp16(sb + nbo + tid * 16, ip + tid * 16);
            asm volatile("cp.async.commit_group;" ::: "memory");
        }

        const int bbase = ch * GCH;
#pragma unroll
        for (int i = 0; i < 2; i++) {
            const int bl = w * 4 + 2 * i + half;
            const uint4* idp = (const uint4*)(smem + bufo + bl * 128);
            float4 a = make_float4(0.f, 0.f, 0.f, 0.f);
#pragma unroll
            for (int c8 = 0; c8 < 8; c8++) {
                const uint4 id8 = idp[c8];
                const uint32_t o0 = id8.x & 0xFFFFu, o1 = id8.x >> 16;
                const uint32_t o2 = id8.y & 0xFFFFu, o3 = id8.y >> 16;
                const uint32_t o4 = id8.z & 0xFFFFu, o5 = id8.z >> 16;
                const uint32_t o6 = id8.w & 0xFFFFu, o7 = id8.w >> 16;
                const char* cb = tile + (size_t)(c8 * 8) * 2048;
                const uint2 v0 = *(const uint2*)(cb + o0 + 0 * 2048);
                const uint2 v1 = *(const uint2*)(cb + o1 + 1 * 2048);
                const uint2 v2 = *(const uint2*)(cb + o2 + 2 * 2048);
                const uint2 v3 = *(const uint2*)(cb + o3 + 3 * 2048);
                const uint2 v4 = *(const uint2*)(cb + o4 + 4 * 2048);
                const uint2 v5 = *(const uint2*)(cb + o5 + 5 * 2048);
                const uint2 v6 = *(const uint2*)(cb + o6 + 6 * 2048);
                const uint2 v7 = *(const uint2*)(cb + o7 + 7 * 2048);
                {
                    __half2 s0 = __hadd2(__hadd2(*(const __half2*)&v0.x, *(const __half2*)&v1.x),
                                         __hadd2(*(const __half2*)&v2.x, *(const __half2*)&v3.x));
                    __half2 s1 = __hadd2(__hadd2(*(const __half2*)&v0.y, *(const __half2*)&v1.y),
                                         __hadd2(*(const __half2*)&v2.y, *(const __half2*)&v3.y));
                    const float2 f0 = __half22float2(s0);
                    const float2 f1 = __half22float2(s1);
                    a.x += f0.x; a.y += f0.y; a.z += f1.x; a.w += f1.y;
                }
                {
                    __half2 s0 = __hadd2(__hadd2(*(const __half2*)&v4.x, *(const __half2*)&v5.x),
                                         __hadd2(*(const __half2*)&v6.x, *(const __half2*)&v7.x));
                    __half2 s1 = __hadd2(__hadd2(*(const __half2*)&v4.y, *(const __half2*)&v5.y),
                                         __hadd2(*(const __half2*)&v6.y, *(const __half2*)&v7.y));
                    const float2 f0 = __half22float2(s0);
                    const float2 f1 = __half22float2(s1);
                    a.x += f0.x; a.y += f0.y; a.z += f1.x; a.w += f1.y;
                }
            }
            const int b = bbase + bl;
            if (b < B)
                *(float4*)(out + (size_t)b * OUTW + jt * 64 + l16 * 4) = a;
        }

        if (nx >= nch) break;
        asm volatile("cp.async.wait_group 0;" ::: "memory");
        __syncthreads();
        bufo ^= (IDB0 ^ IDB1);
        ch = nx;
    }
}

// ---------------------------------------------------------------------------
extern "C" void kernel_launch(void* const* d_in, const int* in_sizes, int n_in,
                              void* d_out, int out_size) {
    const float* x   = (const float*)d_in[0];
    const float* S   = (const float*)d_in[1];
    const float* H   = (const float*)d_in[2];
    const float* T   = (const float*)d_in[3];
    const float* LUT = (const float*)d_in[4];
    float*       out = (float*)d_out;

    const int B = in_sizes[0] / (C_ * D_);

    cudaFuncSetAttribute(fused_kernel, cudaFuncAttributeMaxDynamicSharedMemorySize, GSMEM);
    fused_kernel<<<NCTA, 1024, GSMEM>>>(x, S, T, H, LUT, out, B);
}

// round 16
// speedup vs baseline: 1.0543x; 1.0484x over previous
#include <cuda_runtime.h>
#include <cuda_fp16.h>
#include <cstdint>

// Problem constants (fixed shapes per reference)
#define C_    64
#define D_    8
#define K15_  15
#define K16_  16
#define OUTW  512
#define MAXB  32768
#define NJT   8               // j-tiles of 64
#define ROWB  128             // 64 j fp16 per row
#define TROWS 1024            // c*16+e rows per tile
#define TILEB (TROWS * ROWB)  // 131072 B: one jt tile, smem-resident
#define GCH   128             // b per gather chunk
#define GY    18              // CTAs per jt (8*18 = 144, one wave)

// Scratch (no cudaMalloc allowed): zero-initialized device globals.
__device__ uint8_t        g_table[1 << K15_];   // sign pattern -> argmax_j
__device__ unsigned short g_poff[MAXB * C_];    // (b,c) -> e*128 (row byte off)

__device__ __forceinline__ void cp16(uint32_t daddr, const void* src) {
    asm volatile("cp.async.cg.shared.global [%0], [%1], 16;" :: "r"(daddr), "l"(src) : "memory");
}

// ---------------------------------------------------------------------------
// Kernel T: argmax table only (H staged in smem). Small and fast.
// ---------------------------------------------------------------------------
__global__ void __launch_bounds__(256) table_kernel(const float* __restrict__ H) {
    __shared__ float Hs[K15_ * K16_];
    for (int i = threadIdx.x; i < K15_ * K16_; i += 256) Hs[i] = H[i];
    __syncthreads();
    int m = blockIdx.x * blockDim.x + threadIdx.x;
    float h[K16_];
#pragma unroll
    for (int j = 0; j < K16_; j++) h[j] = 0.f;
#pragma unroll
    for (int k = 0; k < K15_; k++) {
        float sgn = ((m >> k) & 1) ? 1.f : -1.f;
#pragma unroll
        for (int j = 0; j < K16_; j++) h[j] += sgn * Hs[k * K16_ + j];
    }
    float best = h[0];
    int   bi = 0;
#pragma unroll
    for (int j = 1; j < K16_; j++)
        if (h[j] > best) { best = h[j]; bi = j; }
    g_table[m] = (uint8_t)bi;
}

// ---------------------------------------------------------------------------
// Kernel P (idx): per (b,c) sign pattern -> argmax -> row byte offset.
// Launched with PDL: stages S/T (input-only) immediately, then waits for the
// table kernel before the main loop (which reads g_table).
// ---------------------------------------------------------------------------
__global__ void __launch_bounds__(256) idx_kernel(const float* __restrict__ x,
                                                  const float* __restrict__ S,
                                                  const float* __restrict__ T,
                                                  int B) {
    __shared__ float S_s[C_ * D_ * 16];
    __shared__ float T_s[C_ * K15_];

    const int tid = threadIdx.x;
    for (int i = tid; i < C_ * D_ * K15_; i += 256) {
        int cd = i / K15_, k = i - cd * K15_;
        S_s[cd * 16 + k] = S[i];
    }
    for (int i = tid; i < C_ * K15_; i += 256) T_s[i] = T[i];
    __syncthreads();

    cudaGridDependencySynchronize();   // g_table ready beyond this point

    const int warp = tid >> 5, lane = tid & 31;
    const int b = blockIdx.x * 32 + lane;
    const float* xrow = x + (size_t)((b < B) ? b : 0) * 512;

    int e8[8];
#pragma unroll
    for (int cc = 0; cc < 8; cc++) {
        const int c = warp * 8 + cc;
        const float4 xa = __ldg((const float4*)(xrow + c * 8));
        const float4 xb = __ldg((const float4*)(xrow + c * 8 + 4));
        float xr[D_] = {xa.x, xa.y, xa.z, xa.w, xb.x, xb.y, xb.z, xb.w};
        float acc[16];
#pragma unroll
        for (int k = 0; k < 16; k++) acc[k] = 0.f;
#pragma unroll
        for (int d = 0; d < D_; d++) {
            const float xd = xr[d];
            const float4* s4 = (const float4*)(S_s + (c * D_ + d) * 16);
            const float4 s0 = s4[0], s1 = s4[1], s2 = s4[2], s3 = s4[3];
            acc[0]  += xd * s0.x; acc[1]  += xd * s0.y; acc[2]  += xd * s0.z; acc[3]  += xd * s0.w;
            acc[4]  += xd * s1.x; acc[5]  += xd * s1.y; acc[6]  += xd * s1.z; acc[7]  += xd * s1.w;
            acc[8]  += xd * s2.x; acc[9]  += xd * s2.y; acc[10] += xd * s2.z; acc[11] += xd * s2.w;
            acc[12] += xd * s3.x; acc[13] += xd * s3.y; acc[14] += xd * s3.z;
        }
        unsigned m = 0;
#pragma unroll
        for (int k = 0; k < K15_; k++)
            if (acc[k] > T_s[c * K15_ + k]) m |= (1u << k);
        e8[cc] = g_table[m];
    }

    if (b < B) {
        uint4 pk;
        pk.x = (uint32_t)(e8[0] << 7) | ((uint32_t)(e8[1] << 7) << 16);
        pk.y = (uint32_t)(e8[2] << 7) | ((uint32_t)(e8[3] << 7) << 16);
        pk.z = (uint32_t)(e8[4] << 7) | ((uint32_t)(e8[5] << 7) << 16);
        pk.w = (uint32_t)(e8[6] << 7) | ((uint32_t)(e8[7] << 7) << 16);
        *(uint4*)(g_poff + (size_t)b * C_ + warp * 8) = pk;
    }
}

// ---------------------------------------------------------------------------
// Kernel G (gather): out[b, jt*64+l16*4..+4) = sum_c tile[c*16+e][slice]
// Launched with PDL: converts its own 128 KB jt tile fp32->fp16 straight from
// LUT (input-only, overlaps the idx kernel's tail), THEN waits for idx before
// streaming ids. Grid 8 x GY = 144 CTAs, 1024 thr; id chunks (128 b x 128 B)
// double-buffered via cp.async. Warp owns 4 b per chunk (2 per iter, half-
// split). Per (2b, 8c): one uint4 id LDS.128 + 8 LDS.64 row gathers + two
// 4-term fp16 trees per 4-c group + fp32 flush (numerics frozen since R10).
// smem: id buf0 @0 (16 KB), buf1 @16384, tile @32768 (128 KB) = 160 KB.
// ---------------------------------------------------------------------------
#define IDB0 0u
#define IDB1 16384u
#define TOFF 32768u
#define GSMEM (TOFF + TILEB)

__global__ void __launch_bounds__(1024, 1) gather_kernel(const float* __restrict__ LUT,
                                                         float* __restrict__ out, int B) {
    extern __shared__ char smem[];
    const int tid = threadIdx.x, w = tid >> 5, lane = tid & 31;
    const int half = lane >> 4, l16 = lane & 15;
    const int jt = blockIdx.x;
    const uint32_t sb = (uint32_t)__cvta_generic_to_shared(smem);
    const int nch = (B + GCH - 1) / GCH;

    // ---- prologue A: convert own jt tile fp32 -> fp16 (depends only on input LUT)
    {
        const int seg = tid & 15;
#pragma unroll
        for (int it = 0; it < 16; it++) {
            const int row = (tid >> 4) + it * 64;
            const float4 a = __ldg((const float4*)(LUT + (size_t)row * OUTW + jt * 64 + seg * 4));
            __half2 h0 = __floats2half2_rn(a.x, a.y);
            __half2 h1 = __floats2half2_rn(a.z, a.w);
            uint2 v;
            v.x = *(uint32_t*)&h0; v.y = *(uint32_t*)&h1;
            *(uint2*)(smem + TOFF + (size_t)row * ROWB + seg * 8) = v;
        }
    }

    cudaGridDependencySynchronize();   // g_poff (idx output) ready beyond this point

    // ---- prologue B: ids for first chunk
    {
        const unsigned char* ip = (const unsigned char*)g_poff + (size_t)blockIdx.y * GCH * 128;
        cp16(sb + IDB0 + tid * 16, ip + tid * 16);
        asm volatile("cp.async.commit_group;" ::: "memory");
        asm volatile("cp.async.wait_group 0;" ::: "memory");
    }
    __syncthreads();   // ids + converted tile visible to all warps

    const char* tile = smem + TOFF + l16 * 8;   // lane's 8B j-slice within each row

    int ch = blockIdx.y;
    uint32_t bufo = IDB0;
    while (ch < nch) {
        const int nx = ch + GY;
        if (nx < nch) {   // prefetch next chunk's ids into the other buffer
            const uint32_t nbo = bufo ^ (IDB0 ^ IDB1);
            const unsigned char* ip = (const unsigned char*)g_poff + (size_t)nx * GCH * 128;
            cp16(sb + nbo + tid * 16, ip + tid * 16);
            asm volatile("cp.async.commit_group;" ::: "memory");
        }

        const int bbase = ch * GCH;
#pragma unroll
        for (int i = 0; i < 2; i++) {
            const int bl = w * 4 + 2 * i + half;
            const uint4* idp = (const uint4*)(smem + bufo + bl * 128);
            float4 a = make_float4(0.f, 0.f, 0.f, 0.f);
#pragma unroll
            for (int c8 = 0; c8 < 8; c8++) {
                const uint4 id8 = idp[c8];                       // LDS.128 broadcast / half
                const uint32_t o0 = id8.x & 0xFFFFu, o1 = id8.x >> 16;
                const uint32_t o2 = id8.y & 0xFFFFu, o3 = id8.y >> 16;
                const uint32_t o4 = id8.z & 0xFFFFu, o5 = id8.z >> 16;
                const uint32_t o6 = id8.w & 0xFFFFu, o7 = id8.w >> 16;
                const char* cb = tile + (size_t)(c8 * 8) * 2048;
                const uint2 v0 = *(const uint2*)(cb + o0 + 0 * 2048);
                const uint2 v1 = *(const uint2*)(cb + o1 + 1 * 2048);
                const uint2 v2 = *(const uint2*)(cb + o2 + 2 * 2048);
                const uint2 v3 = *(const uint2*)(cb + o3 + 3 * 2048);
                const uint2 v4 = *(const uint2*)(cb + o4 + 4 * 2048);
                const uint2 v5 = *(const uint2*)(cb + o5 + 5 * 2048);
                const uint2 v6 = *(const uint2*)(cb + o6 + 6 * 2048);
                const uint2 v7 = *(const uint2*)(cb + o7 + 7 * 2048);
                {
                    __half2 s0 = __hadd2(__hadd2(*(const __half2*)&v0.x, *(const __half2*)&v1.x),
                                         __hadd2(*(const __half2*)&v2.x, *(const __half2*)&v3.x));
                    __half2 s1 = __hadd2(__hadd2(*(const __half2*)&v0.y, *(const __half2*)&v1.y),
                                         __hadd2(*(const __half2*)&v2.y, *(const __half2*)&v3.y));
                    const float2 f0 = __half22float2(s0);
                    const float2 f1 = __half22float2(s1);
                    a.x += f0.x; a.y += f0.y; a.z += f1.x; a.w += f1.y;
                }
                {
                    __half2 s0 = __hadd2(__hadd2(*(const __half2*)&v4.x, *(const __half2*)&v5.x),
                                         __hadd2(*(const __half2*)&v6.x, *(const __half2*)&v7.x));
                    __half2 s1 = __hadd2(__hadd2(*(const __half2*)&v4.y, *(const __half2*)&v5.y),
                                         __hadd2(*(const __half2*)&v6.y, *(const __half2*)&v7.y));
                    const float2 f0 = __half22float2(s0);
                    const float2 f1 = __half22float2(s1);
                    a.x += f0.x; a.y += f0.y; a.z += f1.x; a.w += f1.y;
                }
            }
            const int b = bbase + bl;
            if (b < B)
                *(float4*)(out + (size_t)b * OUTW + jt * 64 + l16 * 4) = a;
        }

        if (nx >= nch) break;
        asm volatile("cp.async.wait_group 0;" ::: "memory");
        __syncthreads();                 // old buffer drained + new ids visible
        bufo ^= (IDB0 ^ IDB1);
        ch = nx;
    }
}

// ---------------------------------------------------------------------------
extern "C" void kernel_launch(void* const* d_in, const int* in_sizes, int n_in,
                              void* d_out, int out_size) {
    const float* x   = (const float*)d_in[0];
    const float* S   = (const float*)d_in[1];
    const float* H   = (const float*)d_in[2];
    const float* T   = (const float*)d_in[3];
    const float* LUT = (const float*)d_in[4];
    float*       out = (float*)d_out;

    const int B = in_sizes[0] / (C_ * D_);

    // 1) argmax table (plain launch)
    table_kernel<<<(1 << K15_) / 256, 256>>>(H);

    // 2) idx with PDL: overlaps its S/T staging with the table kernel tail
    {
        cudaLaunchConfig_t cfg = {};
        cfg.gridDim = dim3((B + 31) / 32);
        cfg.blockDim = dim3(256);
        cfg.dynamicSmemBytes = 0;
        cfg.stream = 0;
        cudaLaunchAttribute at[1];
        at[0].id = cudaLaunchAttributeProgrammaticStreamSerialization;
        at[0].val.programmaticStreamSerializationAllowed = 1;
        cfg.attrs = at;
        cfg.numAttrs = 1;
        cudaLaunchKernelEx(&cfg, idx_kernel, x, S, T, B);
    }

    // 3) gather with PDL: overlaps its LUT->fp16 tile conversion with idx tail
    cudaFuncSetAttribute(gather_kernel, cudaFuncAttributeMaxDynamicSharedMemorySize, GSMEM);
    {
        cudaLaunchConfig_t cfg = {};
        cfg.gridDim = dim3(NJT, GY);
        cfg.blockDim = dim3(1024);
        cfg.dynamicSmemBytes = GSMEM;
        cfg.stream = 0;
        cudaLaunchAttribute at[1];
        at[0].id = cudaLaunchAttributeProgrammaticStreamSerialization;
        at[0].val.programmaticStreamSerializationAllowed = 1;
        cfg.attrs = at;
        cfg.numAttrs = 1;
        cudaLaunchKernelEx(&cfg, gather_kernel, LUT, out, B);
    }
}